// round 1
// baseline (speedup 1.0000x reference)
#include <cuda_runtime.h>
#include <cstdint>

// Problem constants
#define BB   128      // batch
#define TT   1024     // time steps
#define HH   512      // hidden
#define IIN  17       // input features
#define OOUT 17       // output features

#define NBLK 128      // persistent grid size (<= SM count, co-resident)
#define NTHR 256
#define KC   128      // K chunk staged in smem
#define ASTR 132      // padded As row stride (floats)

// ---------------- device scratch (allowed: __device__ globals) ----------------
__device__ float g_h0[2][BB * HH];
__device__ float g_h1[2][BB * HH];
__device__ float g_y0[(size_t)TT * BB * HH];   // layer0 outputs, [t][b][j]

__device__ unsigned          g_bar_cnt = 0;
__device__ volatile unsigned g_bar_sense = 0;

// ---------------- grid-wide spin barrier (sense reversing) ----------------
// Each kernel must execute an EVEN number of barriers so (cnt,sense) return to
// (0,0) for the next graph replay.
__device__ __forceinline__ void grid_barrier(unsigned* lsense)
{
    __syncthreads();
    if (threadIdx.x == 0) {
        unsigned s = *lsense ^ 1u;
        *lsense = s;
        __threadfence();                       // publish our global writes
        unsigned prev = atomicAdd(&g_bar_cnt, 1u);
        if (prev == NBLK - 1u) {
            atomicExch(&g_bar_cnt, 0u);        // reset for next barrier
            __threadfence();
            g_bar_sense = s;                   // release
        } else {
            while (g_bar_sense != s) { }       // spin on L2
        }
        __threadfence();
    }
    __syncthreads();
}

// ---------------- shared GEMM-chunk inner loop ----------------
// acc[2][4]: 2 batches (tb, tb+16) x 4 gates for cell tj.
__device__ __forceinline__ void gemm_chunk(const float* __restrict__ As,
                                           const float* __restrict__ Ws,
                                           int tb, int tj, float acc[2][4])
{
#pragma unroll 8
    for (int k = 0; k < KC; k += 4) {
        float4 a0 = *(const float4*)(As + tb * ASTR + k);
        float4 a1 = *(const float4*)(As + (tb + 16) * ASTR + k);
#pragma unroll
        for (int g = 0; g < 4; ++g) {
            float4 w = *(const float4*)(Ws + (tj * 4 + g) * KC + k);
            acc[0][g] = fmaf(a0.x, w.x, acc[0][g]);
            acc[0][g] = fmaf(a0.y, w.y, acc[0][g]);
            acc[0][g] = fmaf(a0.z, w.z, acc[0][g]);
            acc[0][g] = fmaf(a0.w, w.w, acc[0][g]);
            acc[1][g] = fmaf(a1.x, w.x, acc[1][g]);
            acc[1][g] = fmaf(a1.y, w.y, acc[1][g]);
            acc[1][g] = fmaf(a1.z, w.z, acc[1][g]);
            acc[1][g] = fmaf(a1.w, w.w, acc[1][g]);
        }
    }
}

__device__ __forceinline__ float sigf(float v) { return 1.f / (1.f + expf(-v)); }

// ---------------- Layer 0 ----------------
// smem layout (floats): Ws[64*128]=8192 | As[32*132]=4224 | Wi[64*17]=1088 |
//                       Xs[32*17]=544   | cb[64]
#define SM0_WS 0
#define SM0_AS 8192
#define SM0_WI 12416
#define SM0_XS 13504
#define SM0_CB 14048
#define SM0_FLOATS 14112

extern "C" __global__ void __launch_bounds__(NTHR, 1)
lstm_l0(const float* __restrict__ x,
        const float* __restrict__ wih, const float* __restrict__ whh,
        const float* __restrict__ bih, const float* __restrict__ bhh)
{
    extern __shared__ float sm[];
    float* Ws = sm + SM0_WS;
    float* As = sm + SM0_AS;
    float* Wi = sm + SM0_WI;
    float* Xs = sm + SM0_XS;
    float* cb = sm + SM0_CB;

    const int tid = threadIdx.x;
    const int tb = tid & 15, tj = tid >> 4;
    const int b0 = (blockIdx.x >> 5) * 32;     // batch-group
    const int j0 = (blockIdx.x & 31) * 16;     // cell-group

    // persistent input weights + combined bias
    for (int idx = tid; idx < 64 * IIN; idx += NTHR) {
        int r = idx / IIN, k = idx - r * IIN;
        int jj = r >> 2, g = r & 3;
        Wi[idx] = wih[(size_t)(g * HH + j0 + jj) * IIN + k];
    }
    if (tid < 64) {
        int jj = tid >> 2, g = tid & 3;
        int row = g * HH + j0 + jj;
        cb[tid] = bih[row] + bhh[row];
    }
    // zero our slice of h ping buffer 0 (read at t=0)
#pragma unroll
    for (int u = 0; u < 2; ++u) {
        int b = b0 + tb + u * 16;
        __stcg(&g_h0[0][b * HH + j0 + tj], 0.f);
    }

    unsigned lsense = 0;
    grid_barrier(&lsense);                     // barrier #1

    float cst[2] = {0.f, 0.f};

    for (int t = 0; t < TT; ++t) {
        const int rb = t & 1, wb = rb ^ 1;

        // stage x_t tile
        for (int idx = tid; idx < 32 * IIN; idx += NTHR) {
            int r = idx / IIN, k = idx - r * IIN;
            Xs[idx] = x[((size_t)(b0 + r) * TT + t) * IIN + k];
        }
        __syncthreads();

        float acc[2][4];
#pragma unroll
        for (int g = 0; g < 4; ++g) { acc[0][g] = cb[tj * 4 + g]; acc[1][g] = acc[0][g]; }

        // input projection part (K = 17)
#pragma unroll
        for (int k = 0; k < IIN; ++k) {
            float a0 = Xs[tb * IIN + k];
            float a1 = Xs[(tb + 16) * IIN + k];
#pragma unroll
            for (int g = 0; g < 4; ++g) {
                float w = Wi[(tj * 4 + g) * IIN + k];
                acc[0][g] = fmaf(a0, w, acc[0][g]);
                acc[1][g] = fmaf(a1, w, acc[1][g]);
            }
        }

        // recurrent part: K = 512 in 4 chunks
        const float* hprev = g_h0[rb];
        for (int kc = 0; kc < HH / KC; ++kc) {
            const int k0 = kc * KC;
            __syncthreads();
            for (int idx = tid; idx < 32 * (KC / 4); idx += NTHR) {
                int r = idx >> 5, c4 = idx & 31;
                float4 v = __ldcg((const float4*)(hprev + (size_t)(b0 + r) * HH + k0) + c4);
                *(float4*)(As + r * ASTR + c4 * 4) = v;
            }
            for (int idx = tid; idx < 64 * (KC / 4); idx += NTHR) {
                int r = idx >> 5, c4 = idx & 31;
                int jj = r >> 2, g = r & 3;
                const float4* wr = (const float4*)(whh + (size_t)(g * HH + j0 + jj) * HH + k0);
                *(float4*)(Ws + r * KC + c4 * 4) = wr[c4];
            }
            __syncthreads();
            gemm_chunk(As, Ws, tb, tj, acc);
        }

        // cell update + publish h
#pragma unroll
        for (int u = 0; u < 2; ++u) {
            float ig = sigf(acc[u][0]);
            float fg = sigf(acc[u][1]);
            float gg = tanhf(acc[u][2]);
            float og = sigf(acc[u][3]);
            cst[u] = fg * cst[u] + ig * gg;
            float h = og * tanhf(cst[u]);
            int b = b0 + tb + u * 16;
            __stcg(&g_h0[wb][b * HH + j0 + tj], h);
            __stcg(&g_y0[((size_t)t * BB + b) * HH + j0 + tj], h);
        }

        grid_barrier(&lsense);                 // barriers #2..#1025
    }
    grid_barrier(&lsense);                     // barrier #1026 (even parity)
}

// ---------------- Layer 1 ----------------
// K = 1024 concat: chunks 0..3 from y0[t] with wih1, chunks 4..7 from h with whh1.
#define SM1_WS 0
#define SM1_AS 8192
#define SM1_CB 12416
#define SM1_FLOATS 12480

extern "C" __global__ void __launch_bounds__(NTHR, 1)
lstm_l1(const float* __restrict__ wih, const float* __restrict__ whh,
        const float* __restrict__ bih, const float* __restrict__ bhh)
{
    extern __shared__ float sm[];
    float* Ws = sm + SM1_WS;
    float* As = sm + SM1_AS;
    float* cb = sm + SM1_CB;

    const int tid = threadIdx.x;
    const int tb = tid & 15, tj = tid >> 4;
    const int b0 = (blockIdx.x >> 5) * 32;
    const int j0 = (blockIdx.x & 31) * 16;

    if (tid < 64) {
        int jj = tid >> 2, g = tid & 3;
        int row = g * HH + j0 + jj;
        cb[tid] = bih[row] + bhh[row];
    }
#pragma unroll
    for (int u = 0; u < 2; ++u) {
        int b = b0 + tb + u * 16;
        __stcg(&g_h1[0][b * HH + j0 + tj], 0.f);
    }

    unsigned lsense = 0;
    grid_barrier(&lsense);

    float cst[2] = {0.f, 0.f};

    for (int t = 0; t < TT; ++t) {
        const int rb = t & 1, wb = rb ^ 1;

        float acc[2][4];
#pragma unroll
        for (int g = 0; g < 4; ++g) { acc[0][g] = cb[tj * 4 + g]; acc[1][g] = acc[0][g]; }

        for (int kc = 0; kc < 8; ++kc) {
            const bool isX = (kc < 4);
            const int  k0  = (isX ? kc : kc - 4) * KC;
            const float* asrc = isX ? (g_y0 + (size_t)t * BB * HH) : g_h1[rb];
            const float* wsrc = isX ? wih : whh;

            __syncthreads();
            for (int idx = tid; idx < 32 * (KC / 4); idx += NTHR) {
                int r = idx >> 5, c4 = idx & 31;
                float4 v = __ldcg((const float4*)(asrc + (size_t)(b0 + r) * HH + k0) + c4);
                *(float4*)(As + r * ASTR + c4 * 4) = v;
            }
            for (int idx = tid; idx < 64 * (KC / 4); idx += NTHR) {
                int r = idx >> 5, c4 = idx & 31;
                int jj = r >> 2, g = r & 3;
                const float4* wr = (const float4*)(wsrc + (size_t)(g * HH + j0 + jj) * HH + k0);
                *(float4*)(Ws + r * KC + c4 * 4) = wr[c4];
            }
            __syncthreads();
            gemm_chunk(As, Ws, tb, tj, acc);
        }

#pragma unroll
        for (int u = 0; u < 2; ++u) {
            float ig = sigf(acc[u][0]);
            float fg = sigf(acc[u][1]);
            float gg = tanhf(acc[u][2]);
            float og = sigf(acc[u][3]);
            cst[u] = fg * cst[u] + ig * gg;
            float h = og * tanhf(cst[u]);
            int b = b0 + tb + u * 16;
            __stcg(&g_h1[wb][b * HH + j0 + tj], h);
        }

        grid_barrier(&lsense);
    }
    grid_barrier(&lsense);                     // even parity
    // final h (t=1023 wrote wb=0) lives in g_h1[0]
}

// ---------------- Final linear: out[b,o] = h_last[b,:] . lin_w[o,:] + lin_b[o]
extern "C" __global__ void final_linear(const float* __restrict__ lin_w,
                                        const float* __restrict__ lin_b,
                                        float* __restrict__ out)
{
    __shared__ float wrow[HH];
    int o = blockIdx.x;
    for (int k = threadIdx.x; k < HH; k += 128) wrow[k] = lin_w[o * HH + k];
    __syncthreads();
    const float* hr = g_h1[0] + (size_t)threadIdx.x * HH;
    float acc = 0.f;
#pragma unroll 4
    for (int k = 0; k < HH; k += 4) {
        float4 hv = *(const float4*)(hr + k);
        acc = fmaf(hv.x, wrow[k + 0], acc);
        acc = fmaf(hv.y, wrow[k + 1], acc);
        acc = fmaf(hv.z, wrow[k + 2], acc);
        acc = fmaf(hv.w, wrow[k + 3], acc);
    }
    out[threadIdx.x * OOUT + o] = acc + lin_b[o];
}

// ---------------- launch ----------------
extern "C" void kernel_launch(void* const* d_in, const int* in_sizes, int n_in,
                              void* d_out, int out_size)
{
    const float* x     = (const float*)d_in[0];
    const float* wih0  = (const float*)d_in[1];
    const float* whh0  = (const float*)d_in[2];
    const float* bih0  = (const float*)d_in[3];
    const float* bhh0  = (const float*)d_in[4];
    const float* wih1  = (const float*)d_in[5];
    const float* whh1  = (const float*)d_in[6];
    const float* bih1  = (const float*)d_in[7];
    const float* bhh1  = (const float*)d_in[8];
    const float* lin_w = (const float*)d_in[9];
    const float* lin_b = (const float*)d_in[10];

    const int smem0 = SM0_FLOATS * 4;
    const int smem1 = SM1_FLOATS * 4;
    cudaFuncSetAttribute(lstm_l0, cudaFuncAttributeMaxDynamicSharedMemorySize, smem0);
    cudaFuncSetAttribute(lstm_l1, cudaFuncAttributeMaxDynamicSharedMemorySize, smem1);

    lstm_l0<<<NBLK, NTHR, smem0>>>(x, wih0, whh0, bih0, bhh0);
    lstm_l1<<<NBLK, NTHR, smem1>>>(wih1, whh1, bih1, bhh1);
    final_linear<<<OOUT, 128>>>(lin_w, lin_b, (float*)d_out);
}